// round 16
// baseline (speedup 1.0000x reference)
#include <cuda_runtime.h>
#include <cuda_bf16.h>
#include <math_constants.h>

#define NB   2
#define NCI  32
#define NCO  32
#define SCALE 3.814697265625e-06f  // 1/64^3

// ---------------- scratch (device globals) -----------------------------------
__device__ float T2[64*64*16*8*2];      // [bc][x][ky][kz]c      4.2 MB
__device__ float T3[64*16*16*8];        // [bc][kx][ky][kz]      0.5 MB
__device__ float T4[64*16*16*8*2];      // [bco][mx][my][kz]c    1.0 MB

// twiddle tables (small, L2-resident)
__device__ __align__(16) float gFY[64*32];    // [y][ky]c forward (c,-s)
__device__ __align__(16) float gFX[64*32];    // [x][kx]c forward
__device__ __align__(16) float gFZp[16*4*4];  // packed quad: [g][c] (e_c, e_{c+4})
__device__ __align__(16) float gIY[16*64];    // [my][yy]c inverse, yy<32
__device__ __align__(16) float gIZp[32*20];   // [zz][kz]c padded 20, scaled
__device__ __align__(16) float gEX[32*32];    // [xh][mx]c inverse

__device__ __forceinline__ int kmap(int m) { return (m < 8) ? m : (m + 48); }

// ---------------- one-shot twiddle init (16 blocks) ---------------------------
__global__ void k_init() {
    int g = blockIdx.x * 256 + threadIdx.x;   // 4096 threads
    if (g < 1024) {                            // gFY, gFX
        int y = g >> 4, ky = g & 15;
        float s, c; sincospif((float)(y*kmap(ky)) / 32.0f, &s, &c);
        gFY[y*32 + ky*2] = c; gFY[y*32 + ky*2 + 1] = -s;
        gFX[y*32 + ky*2] = c; gFX[y*32 + ky*2 + 1] = -s;
    }
    if (g < 64) {                              // gFZp
        int q = g >> 2, c = g & 3;
        float s0, c0, s1, c1;
        sincospif((float)(q*c) / 32.0f, &s0, &c0);
        sincospif((float)(q*(c+4)) / 32.0f, &s1, &c1);
        *(float4*)&gFZp[g*4] = make_float4(c0, -s0, c1, -s1);
    }
    if (g < 512) {                             // gIY [my][yy]c, yy<32
        int my = g >> 5, yy = g & 31;
        float s, c; sincospif((float)(yy*kmap(my)) / 32.0f, &s, &c);
        gIY[my*64 + yy*2] = c; gIY[my*64 + yy*2 + 1] = s;
    }
    if (g < 256) {                             // gIZp [zz][kz]c padded 20
        int zz = g >> 3, kz = g & 7;
        float s, c; sincospif((float)(zz*kz) / 32.0f, &s, &c);
        gIZp[zz*20 + kz*2] = c * SCALE; gIZp[zz*20 + kz*2 + 1] = s * SCALE;
    }
    if (g < 512) {                             // gEX [xh][mx]c
        int xh = g >> 4, mx = g & 15;
        float s, c; sincospif((float)(xh*kmap(mx)) / 32.0f, &s, &c);
        gEX[xh*32 + mx*2] = c; gEX[xh*32 + mx*2 + 1] = s;
    }
}

// ---------- F12: fused z-reduce + y-reduce  x -> T2[bc][x][ky][kz]c ----------
// grid 1024 = 64 bc * 16 x-quads, 256 threads.
__global__ void k_f12(const float* __restrict__ gx) {
    __shared__ float sxp[64*68];       // [y][perm(z)]: quad contiguous
    __shared__ float sA[4*8*130];      // [xi][kz][y]c  row stride 130
    __shared__ __align__(16) float sFZp[16*4*4];
    __shared__ __align__(16) float sFY[64*32];
    int blk = blockIdx.x;
    int bc = blk >> 4;
    int x0 = (blk & 15) << 2;
    int t = threadIdx.x;
    if (t < 64) *(float4*)&sFZp[t*4] = *(const float4*)&gFZp[t*4];
    #pragma unroll
    for (int j = 0; j < 2; j++)
        *(float4*)&sFY[(t + j*256)*4] = *(const float4*)&gFY[(t + j*256)*4];

    int c = t & 3;         // kz class: handles kz = c and c+4
    int y = t >> 2;        // 0..63
    for (int xi = 0; xi < 4; xi++) {
        __syncthreads();
        const float* src = gx + ((size_t)bc*64 + x0 + xi)*4096;
        #pragma unroll
        for (int i4 = 0; i4 < 4; i4++) {
            int i = (t + i4*256) << 2;
            float4 v = *(const float4*)&src[i];
            int z0 = i & 63, yy = i >> 6;
            float* d = &sxp[yy*68 + (z0 & 15)*4 + (z0 >> 4)];
            d[0] = v.x; d[4] = v.y; d[8] = v.z; d[12] = v.w;
        }
        __syncthreads();
        float aR0=0, aI0=0, aR1=0, aI1=0;
        const float* px = &sxp[y*68];
        #pragma unroll 4
        for (int g = 0; g < 16; g++) {
            float4 v = *(const float4*)&px[g*4];   // z=g, g+16, g+32, g+48
            float4 e = *(const float4*)&sFZp[(g*4 + c)*4];
            if ((c & 1) == 0) {
                float f = (c == 0) ? (v.x+v.z) + (v.y+v.w) : (v.x+v.z) - (v.y+v.w);
                aR0 += f*e.x; aI0 += f*e.y;
                aR1 += f*e.z; aI1 += f*e.w;
            } else {
                float uR = v.x - v.z;
                float uI = (c == 1) ? (v.w - v.y) : (v.y - v.w);
                aR0 += uR*e.x - uI*e.y;  aI0 += uR*e.y + uI*e.x;
                aR1 += uR*e.z - uI*e.w;  aI1 += uR*e.w + uI*e.z;
            }
        }
        float* pa = &sA[xi*1040 + c*130 + y*2];
        *(float2*)&pa[0]   = make_float2(aR0, aI0);    // kz = c
        *(float2*)&pa[520] = make_float2(aR1, aI1);    // kz = c + 4
    }
    __syncthreads();
    // stage B: y-reduce, radix-4 fold.
    int xi2 = t >> 6;
    int u   = t & 63;
    int ky0 = (u >> 3) << 1;   // even ky; pair {ky0, ky0+1}
    int kz  = u & 7;
    float sgn = ((ky0 & 3) == 0) ? 1.0f : -1.0f;
    float br0=0, bi0=0, br1=0, bi1=0;
    const float* pa = &sA[xi2*1040 + kz*130];
    #pragma unroll 4
    for (int yy = 0; yy < 16; yy++) {
        float2 a1 = *(const float2*)&pa[yy*2];
        float2 a2 = *(const float2*)&pa[(yy+16)*2];
        float2 a3 = *(const float2*)&pa[(yy+32)*2];
        float2 a4 = *(const float2*)&pa[(yy+48)*2];
        float apR = a1.x + a3.x, apI = a1.y + a3.y;
        float bpR = a2.x + a4.x, bpI = a2.y + a4.y;
        float amR = a1.x - a3.x, amI = a1.y - a3.y;
        float bmR = a2.x - a4.x, bmI = a2.y - a4.y;
        float f0R = fmaf(sgn, bpR, apR);
        float f0I = fmaf(sgn, bpI, apI);
        float f1R = fmaf(sgn, bmI, amR);
        float f1I = fmaf(-sgn, bmR, amI);
        float4 e = *(const float4*)&sFY[yy*32 + ky0*2];
        br0 += f0R*e.x - f0I*e.y;  bi0 += f0R*e.y + f0I*e.x;
        br1 += f1R*e.z - f1I*e.w;  bi1 += f1R*e.w + f1I*e.z;
    }
    float* dst = T2 + (((size_t)bc*64 + x0 + xi2)*128 + ky0*8 + kz)*2;
    *(float2*)&dst[0]  = make_float2(br0, bi0);
    *(float2*)&dst[16] = make_float2(br1, bi1);
}

// ---------- F3: x-reduce + Re  T2 -> T3[bc][kx][ky][kz] ----------------------
// grid 1024 = 64 bc * 16 ky, 128 threads.
__global__ void k_f3() {
    __shared__ __align__(16) float sT2[64*16];    // [x][kz]c
    __shared__ __align__(16) float sFX[64*32];    // [x][kx]c
    int blk = blockIdx.x;
    int bc = blk >> 4;
    int ky = blk & 15;
    int t = threadIdx.x;
    #pragma unroll
    for (int j = 0; j < 4; j++)
        *(float4*)&sFX[(t + j*128)*4] = *(const float4*)&gFX[(t + j*128)*4];
    #pragma unroll
    for (int j = 0; j < 2; j++) {
        int i = t + j*128;              // 256 float4 total
        int x = i >> 2, q = i & 3;
        *(float4*)&sT2[x*16 + q*4] =
            *(const float4*)&T2[(((size_t)bc*64 + x)*128 + ky*8)*2 + q*4];
    }
    __syncthreads();
    int kx = t >> 3;
    int kz = t & 7;
    float sgn = (kx & 1) ? -1.0f : 1.0f;
    float acc = 0.f;
    #pragma unroll 8
    for (int x = 0; x < 32; x++) {
        float2 b1 = *(const float2*)&sT2[x*16 + kz*2];
        float2 b2 = *(const float2*)&sT2[(x+32)*16 + kz*2];
        float bR = fmaf(sgn, b2.x, b1.x);
        float bI = fmaf(sgn, b2.y, b1.y);
        float2 e = *(const float2*)&sFX[x*32 + kx*2];
        acc += bR*e.x - bI*e.y;
    }
    T3[(size_t)bc*2048 + kx*128 + ky*8 + kz] = acc;
}

// ---------- C: channel mix  T3 -> T4[bco][m]c --------------------------------
__global__ void k_c(const float* __restrict__ w1r, const float* __restrict__ w1i,
                    const float* __restrict__ w2r, const float* __restrict__ w2i,
                    const float* __restrict__ w3r, const float* __restrict__ w3i,
                    const float* __restrict__ w4r, const float* __restrict__ w4i) {
    __shared__ float red[224][17];
    int blk = blockIdx.x;
    int co = blk >> 4;
    int chunk = blk & 15;
    int t = threadIdx.x;
    int g   = t >> 5;          // ci group 0..7
    int q32 = t & 31;
    int m = ((chunk << 5) + q32) << 2;
    int mx = m >> 7, my = (m >> 3) & 15;
    int sel = ((my >> 3) << 1) | (mx >> 3);
    const float* wr = (sel==0) ? w1r : (sel==1) ? w2r : (sel==2) ? w3r : w4r;
    const float* wi = (sel==0) ? w1i : (sel==1) ? w2i : (sel==2) ? w3i : w4i;
    int woff = co*512 + (mx & 7)*64 + (my & 7)*8 + (m & 7);
    float acc[16];
    #pragma unroll
    for (int j = 0; j < 16; j++) acc[j] = 0.f;
    int ci0 = g << 2;
    #pragma unroll
    for (int cj = 0; cj < 4; cj++) {
        int ci = ci0 + cj;
        float4 x0 = *(const float4*)&T3[(size_t)ci*2048 + m];
        float4 x1 = *(const float4*)&T3[(size_t)(32 + ci)*2048 + m];
        float4 r  = __ldg((const float4*)&wr[(size_t)ci*16384 + woff]);
        float4 iw = __ldg((const float4*)&wi[(size_t)ci*16384 + woff]);
        acc[0] += x0.x*r.x;  acc[1] += x0.x*iw.x;
        acc[2] += x0.y*r.y;  acc[3] += x0.y*iw.y;
        acc[4] += x0.z*r.z;  acc[5] += x0.z*iw.z;
        acc[6] += x0.w*r.w;  acc[7] += x0.w*iw.w;
        acc[8]  += x1.x*r.x;  acc[9]  += x1.x*iw.x;
        acc[10] += x1.y*r.y;  acc[11] += x1.y*iw.y;
        acc[12] += x1.z*r.z;  acc[13] += x1.z*iw.z;
        acc[14] += x1.w*r.w;  acc[15] += x1.w*iw.w;
    }
    if (g > 0) {
        float* pr = red[(g-1)*32 + q32];
        #pragma unroll
        for (int j = 0; j < 16; j++) pr[j] = acc[j];
    }
    __syncthreads();
    if (g == 0) {
        #pragma unroll
        for (int k = 0; k < 7; k++) {
            const float* pr = red[k*32 + q32];
            #pragma unroll
            for (int j = 0; j < 16; j++) acc[j] += pr[j];
        }
        float* d0 = &T4[((size_t)co*2048 + m)*2];
        *(float4*)d0       = make_float4(acc[0], acc[1], acc[2], acc[3]);
        *(float4*)(d0 + 4) = make_float4(acc[4], acc[5], acc[6], acc[7]);
        float* d1 = &T4[((size_t)(32 + co)*2048 + m)*2];
        *(float4*)d1       = make_float4(acc[8],  acc[9],  acc[10], acc[11]);
        *(float4*)(d1 + 4) = make_float4(acc[12], acc[13], acc[14], acc[15]);
    }
}

// ---------- Ixyz: fused x expand + y expand + z expand + Re  T4 -> out -------
// grid 2048 = 64 bco * 32 x-pairs (x, x+32), 256 threads.  (R12 compute core)
__global__ void __launch_bounds__(256, 6) k_ixyz(float* __restrict__ out) {
    __shared__ __align__(16) float sT4[4096];  // [mx][mm]c, mm = my*8+kz
    __shared__ float sU[2][256];      // [xi][my][kz]c
    __shared__ __align__(16) float sEX[32];    // [mx]c for x = xh
    __shared__ __align__(16) float sIY[16*64]; // [my][yy]c, yy < 32
    __shared__ float sA[2][64*20];    // [xi][y][kz]c pad 20
    __shared__ __align__(16) float sIZ[32*20]; // [zz][kz]c pad 20 (scaled)
    int blk = blockIdx.x;
    int bco = blk >> 5;
    int xh  = blk & 31;               // x = xh, xh+32
    int t = threadIdx.x;
    {   // float4 staged T4 load
        const float4* src = (const float4*)&T4[(size_t)bco*4096];
        #pragma unroll
        for (int i4 = 0; i4 < 4; i4++)
            *(float4*)&sT4[(t + i4*256)*4] = __ldg(src + t + i4*256);
    }
    if (t < 256) *(float4*)&sIY[t*4] = *(const float4*)&gIY[t*4];   // 1024 floats
    if (t < 160) *(float4*)&sIZ[t*4] = *(const float4*)&gIZp[t*4];  // 640 floats
    if (t < 8)   *(float4*)&sEX[t*4] = *(const float4*)&gEX[xh*32 + t*4];
    __syncthreads();
    // stage 0: x expand; x and x+32 together via mx-parity
    if (t < 128) {
        int mm = t;
        float reE=0, imE=0, reO=0, imO=0;
        #pragma unroll
        for (int mx = 0; mx < 16; mx++) {
            float2 a = *(const float2*)&sT4[(mx*128 + mm)*2];
            float2 e = *(const float2*)&sEX[mx*2];
            float re = a.x*e.x - a.y*e.y;
            float im = a.x*e.y + a.y*e.x;
            if ((mx & 1) == 0) { reE += re; imE += im; }
            else               { reO += re; imO += im; }
        }
        sU[0][mm*2]   = reE + reO;  sU[0][mm*2+1] = imE + imO;
        sU[1][mm*2]   = reE - reO;  sU[1][mm*2+1] = imE - imO;
    }
    __syncthreads();
    // stage A: y expand for both x slices; y and y+32 together via my-parity
    {
        int kz = t & 7;
        int yy = t >> 3;   // 0..31
        #pragma unroll
        for (int xi = 0; xi < 2; xi++) {
            float reE=0, imE=0, reO=0, imO=0;
            #pragma unroll
            for (int my = 0; my < 16; my++) {
                float2 a = *(const float2*)&sU[xi][my*16 + kz*2];
                float2 e = *(const float2*)&sIY[my*64 + yy*2];
                float re = a.x*e.x - a.y*e.y;
                float im = a.x*e.y + a.y*e.x;
                if ((my & 1) == 0) { reE += re; imE += im; }
                else               { reO += re; imO += im; }
            }
            sA[xi][yy*20 + kz*2]          = reE + reO;
            sA[xi][yy*20 + kz*2 + 1]      = imE + imO;
            sA[xi][(yy+32)*20 + kz*2]     = reE - reO;
            sA[xi][(yy+32)*20 + kz*2 + 1] = imE - imO;
        }
    }
    __syncthreads();
    // stage B: z expand + Re for both x slices; z and z+32 via kz-parity
    int zz = t & 31;        // z pair (zz, zz+32)
    int yg = t >> 5;        // y = yg*8 + j
    float4 ez[4];
    #pragma unroll
    for (int kq = 0; kq < 4; kq++)
        ez[kq] = *(const float4*)&sIZ[zz*20 + kq*4];
    #pragma unroll
    for (int xi = 0; xi < 2; xi++) {
        size_t obase = ((size_t)bco*64 + xh + xi*32)*4096;
        #pragma unroll
        for (int j = 0; j < 8; j++) {
            int y = yg*8 + j;
            float pe = 0.f, po = 0.f;
            #pragma unroll
            for (int kq = 0; kq < 4; kq++) {
                float4 a = *(const float4*)&sA[xi][y*20 + kq*4];
                pe += a.x*ez[kq].x - a.y*ez[kq].y;   // kz = 2kq (even)
                po += a.z*ez[kq].z - a.w*ez[kq].w;   // kz = 2kq+1 (odd)
            }
            out[obase + y*64 + zz]      = pe + po;
            out[obase + y*64 + 32 + zz] = pe - po;
        }
    }
}

// ---------------- launch -----------------------------------------------------
extern "C" void kernel_launch(void* const* d_in, const int* in_sizes, int n_in,
                              void* d_out, int out_size) {
    const float* x   = (const float*)d_in[0];
    const float* w1r = (const float*)d_in[1];
    const float* w1i = (const float*)d_in[2];
    const float* w2r = (const float*)d_in[3];
    const float* w2i = (const float*)d_in[4];
    const float* w3r = (const float*)d_in[5];
    const float* w3i = (const float*)d_in[6];
    const float* w4r = (const float*)d_in[7];
    const float* w4i = (const float*)d_in[8];
    float* out = (float*)d_out;

    k_init<<<16, 256>>>();
    k_f12<<<1024, 256>>>(x);
    k_f3<<<1024, 128>>>();
    k_c<<<512, 256>>>(w1r, w1i, w2r, w2i, w3r, w3i, w4r, w4i);
    k_ixyz<<<2048, 256>>>(out);
}

// round 17
// speedup vs baseline: 1.0566x; 1.0566x over previous
#include <cuda_runtime.h>
#include <cuda_bf16.h>
#include <math_constants.h>

#define NB   2
#define NCI  32
#define NCO  32
#define SCALE 3.814697265625e-06f  // 1/64^3

// ---------------- scratch (device globals) -----------------------------------
__device__ float T2[64*64*16*8*2];      // [bc][x][ky][kz]c      4.2 MB
__device__ float T3[64*16*16*8];        // [bc][kx][ky][kz]      0.5 MB
__device__ float T4[64*16*16*8*2];      // [bco][mx][my][kz]c    1.0 MB

__device__ __forceinline__ int kmap(int m) { return (m < 8) ? m : (m + 48); }

// ---------- F12: fused z-reduce + y-reduce  x -> T2[bc][x][ky][kz]c ----------
// grid 1024 = 64 bc * 16 x-quads, 256 threads.  (R14 configuration)
__global__ void k_f12(const float* __restrict__ gx) {
    __shared__ float sxp[64*68];       // [y][perm(z)]: quad contiguous
    __shared__ float sA[4*8*130];      // [xi][kz][y]c  row stride 130
    __shared__ float sFZp[16*4*4];     // [g][c] float4 = (e_c, e_{c+4})
    __shared__ float sFY[64*32];       // [y][ky]c
    int blk = blockIdx.x;
    int bc = blk >> 4;
    int x0 = (blk & 15) << 2;
    int t = threadIdx.x;
    if (t < 64) {                                 // sFZp
        int g = t >> 2, c = t & 3;
        float s0, c0, s1, c1;
        sincospif((float)(g*c) / 32.0f, &s0, &c0);
        sincospif((float)(g*(c+4)) / 32.0f, &s1, &c1);
        *(float4*)&sFZp[t*4] = make_float4(c0, -s0, c1, -s1);
    }
    for (int j = t; j < 1024; j += 256) {         // sFY: [y][ky]c
        int y = j >> 4, ky = j & 15;
        float s, c; sincospif((float)(y*kmap(ky)) / 32.0f, &s, &c);
        sFY[y*32 + ky*2] = c; sFY[y*32 + ky*2 + 1] = -s;
    }

    int c = t & 3;         // kz class: handles kz = c and c+4
    int y = t >> 2;        // 0..63
    for (int xi = 0; xi < 4; xi++) {
        __syncthreads();
        const float* src = gx + ((size_t)bc*64 + x0 + xi)*4096;
        #pragma unroll
        for (int i4 = 0; i4 < 4; i4++) {
            int i = (t + i4*256) << 2;
            float4 v = *(const float4*)&src[i];
            int z0 = i & 63, yy = i >> 6;
            float* d = &sxp[yy*68 + (z0 & 15)*4 + (z0 >> 4)];
            d[0] = v.x; d[4] = v.y; d[8] = v.z; d[12] = v.w;
        }
        __syncthreads();
        float aR0=0, aI0=0, aR1=0, aI1=0;
        const float* px = &sxp[y*68];
        #pragma unroll 4
        for (int g = 0; g < 16; g++) {
            float4 v = *(const float4*)&px[g*4];   // z=g, g+16, g+32, g+48
            float4 e = *(const float4*)&sFZp[(g*4 + c)*4];
            if ((c & 1) == 0) {
                float f = (c == 0) ? (v.x+v.z) + (v.y+v.w) : (v.x+v.z) - (v.y+v.w);
                aR0 += f*e.x; aI0 += f*e.y;
                aR1 += f*e.z; aI1 += f*e.w;
            } else {
                float uR = v.x - v.z;
                float uI = (c == 1) ? (v.w - v.y) : (v.y - v.w);
                aR0 += uR*e.x - uI*e.y;  aI0 += uR*e.y + uI*e.x;
                aR1 += uR*e.z - uI*e.w;  aI1 += uR*e.w + uI*e.z;
            }
        }
        float* pa = &sA[xi*1040 + c*130 + y*2];
        *(float2*)&pa[0]   = make_float2(aR0, aI0);    // kz = c
        *(float2*)&pa[520] = make_float2(aR1, aI1);    // kz = c + 4
    }
    __syncthreads();
    // stage B: y-reduce, radix-4 fold.
    int xi2 = t >> 6;
    int u   = t & 63;
    int ky0 = (u >> 3) << 1;   // even ky; pair {ky0, ky0+1}
    int kz  = u & 7;
    float sgn = ((ky0 & 3) == 0) ? 1.0f : -1.0f;
    float br0=0, bi0=0, br1=0, bi1=0;
    const float* pa = &sA[xi2*1040 + kz*130];
    #pragma unroll 4
    for (int yy = 0; yy < 16; yy++) {
        float2 a1 = *(const float2*)&pa[yy*2];
        float2 a2 = *(const float2*)&pa[(yy+16)*2];
        float2 a3 = *(const float2*)&pa[(yy+32)*2];
        float2 a4 = *(const float2*)&pa[(yy+48)*2];
        float apR = a1.x + a3.x, apI = a1.y + a3.y;
        float bpR = a2.x + a4.x, bpI = a2.y + a4.y;
        float amR = a1.x - a3.x, amI = a1.y - a3.y;
        float bmR = a2.x - a4.x, bmI = a2.y - a4.y;
        float f0R = fmaf(sgn, bpR, apR);
        float f0I = fmaf(sgn, bpI, apI);
        float f1R = fmaf(sgn, bmI, amR);
        float f1I = fmaf(-sgn, bmR, amI);
        float4 e = *(const float4*)&sFY[yy*32 + ky0*2];
        br0 += f0R*e.x - f0I*e.y;  bi0 += f0R*e.y + f0I*e.x;
        br1 += f1R*e.z - f1I*e.w;  bi1 += f1R*e.w + f1I*e.z;
    }
    float* dst = T2 + (((size_t)bc*64 + x0 + xi2)*128 + ky0*8 + kz)*2;
    *(float2*)&dst[0]  = make_float2(br0, bi0);
    *(float2*)&dst[16] = make_float2(br1, bi1);
}

// ---------- F3: x-reduce + Re  T2 -> T3[bc][kx][ky][kz] ----------------------
// grid 1024 = 64 bc * 16 ky, 128 threads.  float4 T2 staging.
__global__ void k_f3() {
    __shared__ __align__(16) float sT2[64*16];    // [x][kz]c
    __shared__ float sFX[64*32];                  // [x][kx]c
    int blk = blockIdx.x;
    int bc = blk >> 4;
    int ky = blk & 15;
    int t = threadIdx.x;
    for (int j = t; j < 1024; j += 128) {
        int x = j >> 4, kx = j & 15;
        float s, c; sincospif((float)(x*kmap(kx)) / 32.0f, &s, &c);
        sFX[x*32 + kx*2] = c; sFX[x*32 + kx*2 + 1] = -s;
    }
    #pragma unroll
    for (int j = 0; j < 2; j++) {
        int i = t + j*128;              // 256 float4 total
        int x = i >> 2, q = i & 3;
        *(float4*)&sT2[x*16 + q*4] =
            *(const float4*)&T2[(((size_t)bc*64 + x)*128 + ky*8)*2 + q*4];
    }
    __syncthreads();
    int kx = t >> 3;
    int kz = t & 7;
    float sgn = (kx & 1) ? -1.0f : 1.0f;
    float acc = 0.f;
    #pragma unroll 8
    for (int x = 0; x < 32; x++) {
        float2 b1 = *(const float2*)&sT2[x*16 + kz*2];
        float2 b2 = *(const float2*)&sT2[(x+32)*16 + kz*2];
        float bR = fmaf(sgn, b2.x, b1.x);
        float bI = fmaf(sgn, b2.y, b1.y);
        float2 e = *(const float2*)&sFX[x*32 + kx*2];
        acc += bR*e.x - bI*e.y;
    }
    T3[(size_t)bc*2048 + kx*128 + ky*8 + kz] = acc;
}

// ---------- C: channel mix  T3 -> T4[bco][m]c --------------------------------
// grid 1024 = 32 co * 32 chunks (16 quads each), 128 threads.
// 8 ci-groups of 16 threads; smem cross-group reduction.
__global__ void k_c(const float* __restrict__ w1r, const float* __restrict__ w1i,
                    const float* __restrict__ w2r, const float* __restrict__ w2i,
                    const float* __restrict__ w3r, const float* __restrict__ w3i,
                    const float* __restrict__ w4r, const float* __restrict__ w4i) {
    __shared__ float red[112][17];
    int blk = blockIdx.x;
    int co = blk >> 5;
    int chunk = blk & 31;
    int t = threadIdx.x;
    int g   = t >> 4;          // ci group 0..7
    int q16 = t & 15;          // quad within chunk
    int m = ((chunk << 4) + q16) << 2;
    int mx = m >> 7, my = (m >> 3) & 15;
    int sel = ((my >> 3) << 1) | (mx >> 3);
    const float* wr = (sel==0) ? w1r : (sel==1) ? w2r : (sel==2) ? w3r : w4r;
    const float* wi = (sel==0) ? w1i : (sel==1) ? w2i : (sel==2) ? w3i : w4i;
    int woff = co*512 + (mx & 7)*64 + (my & 7)*8 + (m & 7);
    float acc[16];
    #pragma unroll
    for (int j = 0; j < 16; j++) acc[j] = 0.f;
    int ci0 = g << 2;
    #pragma unroll
    for (int cj = 0; cj < 4; cj++) {
        int ci = ci0 + cj;
        float4 x0 = *(const float4*)&T3[(size_t)ci*2048 + m];
        float4 x1 = *(const float4*)&T3[(size_t)(32 + ci)*2048 + m];
        float4 r  = __ldg((const float4*)&wr[(size_t)ci*16384 + woff]);
        float4 iw = __ldg((const float4*)&wi[(size_t)ci*16384 + woff]);
        acc[0] += x0.x*r.x;  acc[1] += x0.x*iw.x;
        acc[2] += x0.y*r.y;  acc[3] += x0.y*iw.y;
        acc[4] += x0.z*r.z;  acc[5] += x0.z*iw.z;
        acc[6] += x0.w*r.w;  acc[7] += x0.w*iw.w;
        acc[8]  += x1.x*r.x;  acc[9]  += x1.x*iw.x;
        acc[10] += x1.y*r.y;  acc[11] += x1.y*iw.y;
        acc[12] += x1.z*r.z;  acc[13] += x1.z*iw.z;
        acc[14] += x1.w*r.w;  acc[15] += x1.w*iw.w;
    }
    if (g > 0) {
        float* pr = red[(g-1)*16 + q16];
        #pragma unroll
        for (int j = 0; j < 16; j++) pr[j] = acc[j];
    }
    __syncthreads();
    if (g == 0) {
        #pragma unroll
        for (int k = 0; k < 7; k++) {
            const float* pr = red[k*16 + q16];
            #pragma unroll
            for (int j = 0; j < 16; j++) acc[j] += pr[j];
        }
        float* d0 = &T4[((size_t)co*2048 + m)*2];
        *(float4*)d0       = make_float4(acc[0], acc[1], acc[2], acc[3]);
        *(float4*)(d0 + 4) = make_float4(acc[4], acc[5], acc[6], acc[7]);
        float* d1 = &T4[((size_t)(32 + co)*2048 + m)*2];
        *(float4*)d1       = make_float4(acc[8],  acc[9],  acc[10], acc[11]);
        *(float4*)(d1 + 4) = make_float4(acc[12], acc[13], acc[14], acc[15]);
    }
}

// ---------- Ixyz: fused x expand + y expand + z expand + Re  T4 -> out -------
// grid 2048 = 64 bco * 32 x-pairs (x, x+32), 256 threads.  (R12/R14 core)
__global__ void __launch_bounds__(256, 6) k_ixyz(float* __restrict__ out) {
    __shared__ __align__(16) float sT4[4096];  // [mx][mm]c, mm = my*8+kz
    __shared__ float sU[2][256];      // [xi][my][kz]c
    __shared__ float sEX[32];         // [mx]c for x = xh
    __shared__ float sIY[16*64];      // [my][yy]c, yy < 32
    __shared__ float sA[2][64*20];    // [xi][y][kz]c pad 20
    __shared__ float sIZ[32*20];      // [zz][kz]c pad 20 (scaled), zz < 32
    int blk = blockIdx.x;
    int bco = blk >> 5;
    int xh  = blk & 31;               // x = xh, xh+32
    int t = threadIdx.x;
    {   // float4 staged T4 load
        const float4* src = (const float4*)&T4[(size_t)bco*4096];
        #pragma unroll
        for (int i4 = 0; i4 < 4; i4++)
            *(float4*)&sT4[(t + i4*256)*4] = __ldg(src + t + i4*256);
    }
    for (int j = t; j < 512; j += 256) {        // sIY [my][yy]c, yy<32
        int my = j >> 5, yy = j & 31;
        float s, c; sincospif((float)(yy*kmap(my)) / 32.0f, &s, &c);
        sIY[my*64 + yy*2] = c; sIY[my*64 + yy*2 + 1] = s;
    }
    if (t < 256) {                              // sIZ [zz][kz]c, zz<32
        int zz = t >> 3, kz = t & 7;
        float s, c; sincospif((float)(zz*kz) / 32.0f, &s, &c);
        sIZ[zz*20 + kz*2] = c * SCALE; sIZ[zz*20 + kz*2 + 1] = s * SCALE;
    }
    if (t < 16) {
        float s, c; sincospif((float)(xh*kmap(t)) / 32.0f, &s, &c);
        sEX[t*2] = c; sEX[t*2+1] = s;
    }
    __syncthreads();
    // stage 0: x expand; x and x+32 together via mx-parity
    if (t < 128) {
        int mm = t;
        float reE=0, imE=0, reO=0, imO=0;
        #pragma unroll
        for (int mx = 0; mx < 16; mx++) {
            float2 a = *(const float2*)&sT4[(mx*128 + mm)*2];
            float2 e = *(const float2*)&sEX[mx*2];
            float re = a.x*e.x - a.y*e.y;
            float im = a.x*e.y + a.y*e.x;
            if ((mx & 1) == 0) { reE += re; imE += im; }
            else               { reO += re; imO += im; }
        }
        sU[0][mm*2]   = reE + reO;  sU[0][mm*2+1] = imE + imO;
        sU[1][mm*2]   = reE - reO;  sU[1][mm*2+1] = imE - imO;
    }
    __syncthreads();
    // stage A: y expand for both x slices; y and y+32 together via my-parity
    {
        int kz = t & 7;
        int yy = t >> 3;   // 0..31
        #pragma unroll
        for (int xi = 0; xi < 2; xi++) {
            float reE=0, imE=0, reO=0, imO=0;
            #pragma unroll
            for (int my = 0; my < 16; my++) {
                float2 a = *(const float2*)&sU[xi][my*16 + kz*2];
                float2 e = *(const float2*)&sIY[my*64 + yy*2];
                float re = a.x*e.x - a.y*e.y;
                float im = a.x*e.y + a.y*e.x;
                if ((my & 1) == 0) { reE += re; imE += im; }
                else               { reO += re; imO += im; }
            }
            sA[xi][yy*20 + kz*2]          = reE + reO;
            sA[xi][yy*20 + kz*2 + 1]      = imE + imO;
            sA[xi][(yy+32)*20 + kz*2]     = reE - reO;
            sA[xi][(yy+32)*20 + kz*2 + 1] = imE - imO;
        }
    }
    __syncthreads();
    // stage B: z expand + Re for both x slices; z and z+32 via kz-parity
    int zz = t & 31;        // z pair (zz, zz+32)
    int yg = t >> 5;        // y = yg*8 + j
    float4 ez[4];
    #pragma unroll
    for (int kq = 0; kq < 4; kq++)
        ez[kq] = *(const float4*)&sIZ[zz*20 + kq*4];
    #pragma unroll
    for (int xi = 0; xi < 2; xi++) {
        size_t obase = ((size_t)bco*64 + xh + xi*32)*4096;
        #pragma unroll
        for (int j = 0; j < 8; j++) {
            int y = yg*8 + j;
            float pe = 0.f, po = 0.f;
            #pragma unroll
            for (int kq = 0; kq < 4; kq++) {
                float4 a = *(const float4*)&sA[xi][y*20 + kq*4];
                pe += a.x*ez[kq].x - a.y*ez[kq].y;   // kz = 2kq (even)
                po += a.z*ez[kq].z - a.w*ez[kq].w;   // kz = 2kq+1 (odd)
            }
            out[obase + y*64 + zz]      = pe + po;
            out[obase + y*64 + 32 + zz] = pe - po;
        }
    }
}

// ---------------- launch -----------------------------------------------------
extern "C" void kernel_launch(void* const* d_in, const int* in_sizes, int n_in,
                              void* d_out, int out_size) {
    const float* x   = (const float*)d_in[0];
    const float* w1r = (const float*)d_in[1];
    const float* w1i = (const float*)d_in[2];
    const float* w2r = (const float*)d_in[3];
    const float* w2i = (const float*)d_in[4];
    const float* w3r = (const float*)d_in[5];
    const float* w3i = (const float*)d_in[6];
    const float* w4r = (const float*)d_in[7];
    const float* w4i = (const float*)d_in[8];
    float* out = (float*)d_out;

    k_f12<<<1024, 256>>>(x);
    k_f3<<<1024, 128>>>();
    k_c<<<1024, 128>>>(w1r, w1i, w2r, w2i, w3r, w3i, w4r, w4i);
    k_ixyz<<<2048, 256>>>(out);
}